// round 1
// baseline (speedup 1.0000x reference)
#include <cuda_runtime.h>
#include <cstddef>

#define NN 50000
#define EE 800000

// ---------------- scratch (device globals: allocation-free) ----------------
__device__ __align__(16) float g_b1[(size_t)NN * 1024];  // h1 / h3 / g2 reuse
__device__ __align__(16) float g_b2[(size_t)NN * 1024];  // h2
__device__ __align__(16) float g_x [(size_t)NN * 512];   // x  (in_net output)
__device__ __align__(16) float g_g [(size_t)NN * 512];   // g = x + agg
__device__ __align__(16) float g_gr[(size_t)NN * 512];   // relu(g@Wg1+bg1)

// ---------------- generic tiled SGEMM: C = relu?(A[MxK] @ B[KxNc] + bias) ---
template <bool RELU>
__global__ void __launch_bounds__(256)
sgemm_kernel(const float* __restrict__ A, const float* __restrict__ B,
             const float* __restrict__ bias, float* __restrict__ C,
             int M, int Nc, int K)
{
    constexpr int BM = 128, BN = 128, BK = 8;
    __shared__ float As[BK][BM];
    __shared__ float Bs[BK][BN];

    const int tid = threadIdx.x;              // 0..255
    const int block_row = blockIdx.y * BM;
    const int block_col = blockIdx.x * BN;

    const int tx = tid & 15;                  // col group (16)
    const int ty = tid >> 4;                  // row group (16)

    // A tile load mapping: 128x8 floats, float4 along K
    const int a_row = tid >> 1;               // 0..127
    const int a_col = (tid & 1) * 4;          // 0 or 4
    // B tile load mapping: 8x128 floats, float4 along N
    const int b_row = tid >> 5;               // 0..7
    const int b_col = (tid & 31) * 4;         // 0..124

    const int gRow = block_row + a_row;
    const int gColB = block_col + b_col;

    float acc[8][8];
#pragma unroll
    for (int i = 0; i < 8; i++)
#pragma unroll
        for (int j = 0; j < 8; j++) acc[i][j] = 0.f;

    for (int k0 = 0; k0 < K; k0 += BK) {
        float4 av = make_float4(0.f, 0.f, 0.f, 0.f);
        if (gRow < M)
            av = *reinterpret_cast<const float4*>(A + (size_t)gRow * K + k0 + a_col);
        As[a_col + 0][a_row] = av.x;
        As[a_col + 1][a_row] = av.y;
        As[a_col + 2][a_row] = av.z;
        As[a_col + 3][a_row] = av.w;

        float4 bv = make_float4(0.f, 0.f, 0.f, 0.f);
        if (gColB < Nc)
            bv = *reinterpret_cast<const float4*>(B + (size_t)(k0 + b_row) * Nc + gColB);
        *reinterpret_cast<float4*>(&Bs[b_row][b_col]) = bv;

        __syncthreads();

#pragma unroll
        for (int kk = 0; kk < BK; kk++) {
            float4 a0 = *reinterpret_cast<const float4*>(&As[kk][ty * 8]);
            float4 a1 = *reinterpret_cast<const float4*>(&As[kk][ty * 8 + 4]);
            float4 b0 = *reinterpret_cast<const float4*>(&Bs[kk][tx * 8]);
            float4 b1 = *reinterpret_cast<const float4*>(&Bs[kk][tx * 8 + 4]);
            float ra[8] = {a0.x, a0.y, a0.z, a0.w, a1.x, a1.y, a1.z, a1.w};
            float rb[8] = {b0.x, b0.y, b0.z, b0.w, b1.x, b1.y, b1.z, b1.w};
#pragma unroll
            for (int i = 0; i < 8; i++)
#pragma unroll
                for (int j = 0; j < 8; j++)
                    acc[i][j] = fmaf(ra[i], rb[j], acc[i][j]);
        }
        __syncthreads();
    }

#pragma unroll
    for (int i = 0; i < 8; i++) {
        int r = block_row + ty * 8 + i;
        if (r < M) {
#pragma unroll
            for (int j = 0; j < 8; j++) {
                int c = block_col + tx * 8 + j;
                if (c < Nc) {
                    float v = acc[i][j] + bias[c];
                    if (RELU) v = fmaxf(v, 0.f);
                    C[(size_t)r * Nc + c] = v;
                }
            }
        }
    }
}

// ---------------- g = x (init before scatter-add) ---------------------------
__global__ void copy_kernel(const float* __restrict__ src, float* __restrict__ dst,
                            size_t n4)
{
    size_t i = (size_t)blockIdx.x * blockDim.x + threadIdx.x;
    if (i < n4)
        reinterpret_cast<float4*>(dst)[i] =
            reinterpret_cast<const float4*>(src)[i];
}

// ---------------- GIN sum aggregation: g[dst] += x[src] ---------------------
// one thread per (edge, 4-float chunk): E * 128 threads
__global__ void scatter_kernel(const float* __restrict__ x,
                               const int* __restrict__ ei,  // [2*E]: src then dst
                               float* __restrict__ g, int E)
{
    long long t = (long long)blockIdx.x * blockDim.x + threadIdx.x;
    int e = (int)(t >> 7);
    if (e >= E) return;
    int c = ((int)t & 127) << 2;
    int s = ei[e];
    int d = ei[E + e];
    float4 v = *reinterpret_cast<const float4*>(x + (size_t)s * 512 + c);
    float* p = g + (size_t)d * 512 + c;
    atomicAdd(p + 0, v.x);
    atomicAdd(p + 1, v.y);
    atomicAdd(p + 2, v.z);
    atomicAdd(p + 3, v.w);
}

// ---------------- launch --------------------------------------------------
extern "C" void kernel_launch(void* const* d_in, const int* in_sizes, int n_in,
                              void* d_out, int out_size)
{
    const float* P    = (const float*)d_in[0];
    const int*   EI   = (const int*)  d_in[1];
    const float* W1   = (const float*)d_in[2];
    const float* b1   = (const float*)d_in[3];
    const float* W2   = (const float*)d_in[4];
    const float* b2   = (const float*)d_in[5];
    const float* W3   = (const float*)d_in[6];
    const float* b3   = (const float*)d_in[7];
    const float* W4   = (const float*)d_in[8];
    const float* b4   = (const float*)d_in[9];
    const float* Win  = (const float*)d_in[10];
    const float* bin_ = (const float*)d_in[11];
    const float* Wg1  = (const float*)d_in[12];
    const float* bg1  = (const float*)d_in[13];
    const float* Wg2  = (const float*)d_in[14];
    const float* bg2  = (const float*)d_in[15];
    const float* Wout = (const float*)d_in[16];
    const float* bout = (const float*)d_in[17];

    float* out  = (float*)d_out;
    float* mask = out;                         // [N,80] first tuple element
    float* feat = out + (size_t)NN * 80;       // [N,80] second tuple element

    float *B1, *B2, *X, *G, *GR;
    cudaGetSymbolAddress((void**)&B1, g_b1);
    cudaGetSymbolAddress((void**)&B2, g_b2);
    cudaGetSymbolAddress((void**)&X,  g_x);
    cudaGetSymbolAddress((void**)&G,  g_g);
    cudaGetSymbolAddress((void**)&GR, g_gr);

    const int M = NN;
    const dim3 blk(256);
    const int rowTiles = (M + 127) / 128;

    // aanet_proj
    sgemm_kernel<true ><<<dim3(1024 / 128, rowTiles), blk>>>(P,  W1, b1, B1, M, 1024, 512);
    sgemm_kernel<true ><<<dim3(1024 / 128, rowTiles), blk>>>(B1, W2, b2, B2, M, 1024, 1024);
    sgemm_kernel<true ><<<dim3(512  / 128, rowTiles), blk>>>(B2, W3, b3, B1, M, 512, 1024);
    sgemm_kernel<false><<<dim3(1,          rowTiles), blk>>>(B1, W4, b4, feat, M, 80, 512);

    // in_net
    sgemm_kernel<false><<<dim3(512 / 128, rowTiles), blk>>>(feat, Win, bin_, X, M, 512, 80);

    // GIN aggregation: g = x + segment_sum(x[src] -> dst)
    {
        size_t n4 = (size_t)NN * 512 / 4;
        copy_kernel<<<(unsigned)((n4 + 255) / 256), blk>>>(X, G, n4);
        long long tot = (long long)EE * 128;
        scatter_kernel<<<(unsigned)((tot + 255) / 256), blk>>>(X, EI, G, EE);
    }

    // GIN MLP
    sgemm_kernel<true ><<<dim3(512 / 128, rowTiles), blk>>>(G,  Wg1, bg1, GR, M, 512, 512);
    sgemm_kernel<false><<<dim3(512 / 128, rowTiles), blk>>>(GR, Wg2, bg2, B1, M, 512, 512);

    // out_net
    sgemm_kernel<false><<<dim3(1, rowTiles), blk>>>(B1, Wout, bout, mask, M, 80, 512);
}

// round 4
// speedup vs baseline: 1.3498x; 1.3498x over previous
#include <cuda_runtime.h>
#include <cuda_bf16.h>
#include <cstdint>
#include <cstddef>

#define NN 50000
#define EE 800000

// ---------------- scratch (device globals: allocation-free) ----------------
__device__ __align__(256) float g_h1[(size_t)NN * 1024];
__device__ __align__(256) float g_h2[(size_t)NN * 1024];
__device__ __align__(256) float g_h3[(size_t)NN * 512];
__device__ __align__(256) float g_gg[(size_t)NN * 512];
__device__ __align__(256) float g_t [(size_t)NN * 80];
__device__ __align__(256) float g_deg[NN];
__device__ __align__(256) __nv_bfloat16 g_ac[(size_t)NN * 3072];  // activation conv
__device__ __align__(256) __nv_bfloat16 g_wc[8454144];            // all weight convs

// ---------------- warp-MMA helpers (baseline sm_80+ PTX only) --------------
__device__ __forceinline__ void ldsm4(uint32_t* r, uint32_t addr) {
    asm volatile("ldmatrix.sync.aligned.m8n8.x4.shared.b16 {%0,%1,%2,%3}, [%4];"
                 : "=r"(r[0]), "=r"(r[1]), "=r"(r[2]), "=r"(r[3]) : "r"(addr));
}
__device__ __forceinline__ void mma_bf16(float* c, const uint32_t* a,
                                         uint32_t b0, uint32_t b1) {
    asm volatile(
        "mma.sync.aligned.m16n8k16.row.col.f32.bf16.bf16.f32 "
        "{%0,%1,%2,%3}, {%4,%5,%6,%7}, {%8,%9}, {%0,%1,%2,%3};"
        : "+f"(c[0]), "+f"(c[1]), "+f"(c[2]), "+f"(c[3])
        : "r"(a[0]), "r"(a[1]), "r"(a[2]), "r"(a[3]), "r"(b0), "r"(b1));
}

// ---------------- bf16 tensor-core GEMM: C = relu?(A @ Bw^T + bias) --------
// A: [M, Kp3] bf16 row-major. Bw: [Np, Kp3] bf16 (pre-transposed, padded).
// Tile 128x128, BK=32, 4-stage cp.async pipeline, 8 warps x (64x32) warp tiles.
// SMEM rows: 32 bf16 = 64B data @ 80B pitch -> conflict-free ldmatrix.
template <bool RELU>
__global__ void __launch_bounds__(256, 2)
gemm_mma(const __nv_bfloat16* __restrict__ A, const __nv_bfloat16* __restrict__ Bw,
         const float* __restrict__ bias, float* __restrict__ C,
         int M, int Nreal, int Kp3)
{
    constexpr int STAGES = 4;
    constexpr int PITCH  = 80;            // bytes per 32-elem K row
    constexpr int TILEB  = 128 * PITCH;   // 10240 per operand tile
    constexpr int STAGEB = 2 * TILEB;

    extern __shared__ char smem[];
    const uint32_t sbase = (uint32_t)__cvta_generic_to_shared(smem);

    const int tid  = threadIdx.x;
    const int lane = tid & 31;
    const int wid  = tid >> 5;
    const int wm   = wid >> 2;            // 0..1 (M direction)
    const int wn   = wid & 3;             // 0..3 (N direction)
    const int block_row = blockIdx.y * 128;
    const int block_col = blockIdx.x * 128;

    const int ld = Kp3 * 2;               // row stride bytes
    const char* Ag = (const char*)A + (size_t)block_row * ld;
    const char* Bg = (const char*)Bw + (size_t)block_col * ld;
    const int KT = Kp3 >> 5;              // k-chunks of 32

    auto load_stage = [&](int s, int kc) {
        uint32_t abuf = sbase + s * STAGEB;
        uint32_t bbuf = abuf + TILEB;
        const char* Ak = Ag + kc * 64;
        const char* Bk = Bg + kc * 64;
#pragma unroll
        for (int it = 0; it < 2; it++) {
            int idx = tid + it * 256;     // 512 16B chunks per tile
            int row = idx >> 2, c = idx & 3;
            int ok = (block_row + row) < M;
            uint32_t da = abuf + row * PITCH + c * 16;
            const char* sa = Ak + (size_t)(ok ? row : 0) * ld + c * 16;
            int sz = ok ? 16 : 0;
            asm volatile("cp.async.cg.shared.global [%0], [%1], 16, %2;"
                         :: "r"(da), "l"(sa), "r"(sz));
            uint32_t db = bbuf + row * PITCH + c * 16;
            asm volatile("cp.async.cg.shared.global [%0], [%1], 16;"
                         :: "r"(db), "l"(Bk + (size_t)row * ld + c * 16));
        }
    };

    float acc[4][4][4];
#pragma unroll
    for (int i = 0; i < 4; i++)
#pragma unroll
        for (int j = 0; j < 4; j++)
#pragma unroll
            for (int k = 0; k < 4; k++) acc[i][j][k] = 0.f;

#pragma unroll
    for (int s = 0; s < STAGES - 1; s++) {
        if (s < KT) load_stage(s, s);
        asm volatile("cp.async.commit_group;" ::: "memory");
    }

    const uint32_t lrow = lane & 15;
    const uint32_t lhi  = (lane >> 4) << 4;   // 0 / 16 bytes

    for (int ks = 0; ks < KT; ks++) {
        asm volatile("cp.async.wait_group %0;" :: "n"(STAGES - 2) : "memory");
        __syncthreads();
        int kn = ks + STAGES - 1;
        if (kn < KT) load_stage(kn & (STAGES - 1), kn);
        asm volatile("cp.async.commit_group;" ::: "memory");

        uint32_t abuf = sbase + (ks & (STAGES - 1)) * STAGEB;
        uint32_t bbuf = abuf + TILEB;
#pragma unroll
        for (int kk = 0; kk < 2; kk++) {          // two k16 steps per chunk
            uint32_t col = kk * 32 + lhi;
            uint32_t afr[4][4];
#pragma unroll
            for (int mt = 0; mt < 4; mt++)
                ldsm4(afr[mt], abuf + (wm * 64 + mt * 16 + lrow) * PITCH + col);
            uint32_t bq[2][4];
#pragma unroll
            for (int nt = 0; nt < 2; nt++)
                ldsm4(bq[nt], bbuf + (wn * 32 + nt * 16 + lrow) * PITCH + col);
#pragma unroll
            for (int mt = 0; mt < 4; mt++)
#pragma unroll
                for (int n8 = 0; n8 < 4; n8++)
                    mma_bf16(acc[mt][n8], afr[mt],
                             bq[n8 >> 1][n8 & 1], bq[n8 >> 1][(n8 & 1) + 2]);
        }
    }

    // epilogue: C-fragment -> bias(+ReLU) -> global (float2 stores)
    const int g = lane >> 2, t = lane & 3;
#pragma unroll
    for (int mt = 0; mt < 4; mt++) {
#pragma unroll
        for (int n8 = 0; n8 < 4; n8++) {
            int c = block_col + wn * 32 + n8 * 8 + t * 2;
            if (c >= Nreal) continue;
            float bx = __ldg(bias + c), by = __ldg(bias + c + 1);
#pragma unroll
            for (int h = 0; h < 2; h++) {
                int r = block_row + wm * 64 + mt * 16 + g + h * 8;
                if (r < M) {
                    float2 v;
                    v.x = acc[mt][n8][h * 2 + 0] + bx;
                    v.y = acc[mt][n8][h * 2 + 1] + by;
                    if (RELU) { v.x = fmaxf(v.x, 0.f); v.y = fmaxf(v.y, 0.f); }
                    *reinterpret_cast<float2*>(C + (size_t)r * Nreal + c) = v;
                }
            }
        }
    }
}

// ---------------- fp32 -> split-bf16 [hi | lo | hi] conversion --------------
__global__ void conv_act(const float* __restrict__ in, __nv_bfloat16* __restrict__ out,
                         int M, int K, int Kp)
{
    int idx = blockIdx.x * blockDim.x + threadIdx.x;
    if (idx >= M * Kp) return;
    int r = idx / Kp;
    int k = idx - r * Kp;
    float x = (k < K) ? in[(size_t)r * K + k] : 0.f;
    __nv_bfloat16 hi = __float2bfloat16(x);
    __nv_bfloat16 lo = __float2bfloat16(x - __bfloat162float(hi));
    size_t b = (size_t)r * 3 * Kp;
    out[b + k] = hi;
    out[b + Kp + k] = lo;
    out[b + 2 * Kp + k] = hi;
}

// W[K,N] fp32 -> [Np, 3*Kp] bf16, row n = [hi | hi | lo]  (pairs with act hi|lo|hi)
__global__ void conv_wt(const float* __restrict__ W, __nv_bfloat16* __restrict__ out,
                        int K, int N, int Kp, int Np)
{
    int idx = blockIdx.x * blockDim.x + threadIdx.x;
    if (idx >= Np * Kp) return;
    int n = idx / Kp;
    int k = idx - n * Kp;
    float x = (k < K && n < N) ? W[(size_t)k * N + n] : 0.f;
    __nv_bfloat16 hi = __float2bfloat16(x);
    __nv_bfloat16 lo = __float2bfloat16(x - __bfloat162float(hi));
    size_t b = (size_t)n * 3 * Kp;
    out[b + k] = hi;
    out[b + Kp + k] = hi;
    out[b + 2 * Kp + k] = lo;
}

// ---------------- GIN aggregation on 80-dim feat ----------------------------
__global__ void k_init_t(const float* __restrict__ feat, float* __restrict__ t,
                         float* __restrict__ deg, int n4, int N)
{
    int i = blockIdx.x * blockDim.x + threadIdx.x;
    if (i < n4)
        reinterpret_cast<float4*>(t)[i] = reinterpret_cast<const float4*>(feat)[i];
    if (i < N) deg[i] = 0.f;
}

__global__ void k_scatter(const float* __restrict__ feat, const int* __restrict__ ei,
                          float* __restrict__ t, float* __restrict__ deg, int E)
{
    int i = blockIdx.x * blockDim.x + threadIdx.x;
    if (i >= E * 20) return;
    int e = i / 20;
    int c = i - e * 20;
    int s = ei[e];
    int d = ei[E + e];
    float4 v = *reinterpret_cast<const float4*>(feat + (size_t)s * 80 + c * 4);
    float* p = t + (size_t)d * 80 + c * 4;
    atomicAdd(p + 0, v.x);
    atomicAdd(p + 1, v.y);
    atomicAdd(p + 2, v.z);
    atomicAdd(p + 3, v.w);
    if (c == 0) atomicAdd(deg + d, 1.f);
}

// g[r][c] += deg[r] * bin[c]
__global__ void k_fixup(float* __restrict__ g, const float* __restrict__ deg,
                        const float* __restrict__ bin, int N)
{
    int i = blockIdx.x * blockDim.x + threadIdx.x;
    if (i >= N * 128) return;
    int r = i >> 7, c4 = i & 127;
    float dg = __ldg(deg + r);
    float4 b = *reinterpret_cast<const float4*>(bin + c4 * 4);
    float4* p = reinterpret_cast<float4*>(g + (size_t)r * 512 + c4 * 4);
    float4 v = *p;
    v.x += dg * b.x; v.y += dg * b.y; v.z += dg * b.z; v.w += dg * b.w;
    *p = v;
}

// ---------------- launch ----------------------------------------------------
static inline unsigned cdiv(long long a, long long b) { return (unsigned)((a + b - 1) / b); }

extern "C" void kernel_launch(void* const* d_in, const int* in_sizes, int n_in,
                              void* d_out, int out_size)
{
    const float* P    = (const float*)d_in[0];
    const int*   EI   = (const int*)  d_in[1];
    const float* W1   = (const float*)d_in[2];
    const float* b1   = (const float*)d_in[3];
    const float* W2   = (const float*)d_in[4];
    const float* b2   = (const float*)d_in[5];
    const float* W3   = (const float*)d_in[6];
    const float* b3   = (const float*)d_in[7];
    const float* W4   = (const float*)d_in[8];
    const float* b4   = (const float*)d_in[9];
    const float* Win  = (const float*)d_in[10];
    const float* bin_ = (const float*)d_in[11];
    const float* Wg1  = (const float*)d_in[12];
    const float* bg1  = (const float*)d_in[13];
    const float* Wg2  = (const float*)d_in[14];
    const float* bg2  = (const float*)d_in[15];
    const float* Wout = (const float*)d_in[16];
    const float* bout = (const float*)d_in[17];

    float* out  = (float*)d_out;
    float* mask = out;
    float* feat = out + (size_t)NN * 80;

    float *H1, *H2, *H3, *GG, *T, *DEG;
    __nv_bfloat16 *AC, *WC;
    cudaGetSymbolAddress((void**)&H1, g_h1);
    cudaGetSymbolAddress((void**)&H2, g_h2);
    cudaGetSymbolAddress((void**)&H3, g_h3);
    cudaGetSymbolAddress((void**)&GG, g_gg);
    cudaGetSymbolAddress((void**)&T,  g_t);
    cudaGetSymbolAddress((void**)&DEG, g_deg);
    cudaGetSymbolAddress((void**)&AC, g_ac);
    cudaGetSymbolAddress((void**)&WC, g_wc);

    // weight conv buffer offsets (elements)
    __nv_bfloat16* W1c   = WC + 0;        // 1024 x 1536
    __nv_bfloat16* W2c   = WC + 1572864;  // 1024 x 3072
    __nv_bfloat16* W3c   = WC + 4718592;  // 512 x 3072
    __nv_bfloat16* W4c   = WC + 6291456;  // 128 x 1536
    __nv_bfloat16* Winc  = WC + 6488064;  // 512 x 384
    __nv_bfloat16* Wg1c  = WC + 6684672;  // 512 x 1536
    __nv_bfloat16* Wg2c  = WC + 7471104;  // 512 x 1536
    __nv_bfloat16* Woutc = WC + 8257536;  // 128 x 1536

    const int M = NN;
    const int SMEM = 4 * 2 * 128 * 80;    // 81920 B
    cudaFuncSetAttribute(gemm_mma<true>,  cudaFuncAttributeMaxDynamicSharedMemorySize, SMEM);
    cudaFuncSetAttribute(gemm_mma<false>, cudaFuncAttributeMaxDynamicSharedMemorySize, SMEM);

    const dim3 blk(256);
    const unsigned rt = cdiv(M, 128);

    // --- weight conversions (tiny) ---
    conv_wt<<<cdiv(1024 * 512, 256), blk>>>(W1,   W1c,   512, 1024, 512, 1024);
    conv_wt<<<cdiv(1024 * 1024, 256), blk>>>(W2,  W2c,  1024, 1024, 1024, 1024);
    conv_wt<<<cdiv(512 * 1024, 256), blk>>>(W3,   W3c,  1024,  512, 1024,  512);
    conv_wt<<<cdiv(128 * 512, 256), blk>>>(W4,    W4c,   512,   80,  512,  128);
    conv_wt<<<cdiv(512 * 128, 256), blk>>>(Win,   Winc,   80,  512,  128,  512);
    conv_wt<<<cdiv(512 * 512, 256), blk>>>(Wg1,   Wg1c,  512,  512,  512,  512);
    conv_wt<<<cdiv(512 * 512, 256), blk>>>(Wg2,   Wg2c,  512,  512,  512,  512);
    conv_wt<<<cdiv(128 * 512, 256), blk>>>(Wout,  Woutc, 512,   80,  512,  128);

    // --- aanet_proj ---
    conv_act<<<cdiv((long long)M * 512, 256), blk>>>(P, AC, M, 512, 512);
    gemm_mma<true><<<dim3(8, rt), blk, SMEM>>>(AC, W1c, b1, H1, M, 1024, 1536);
    conv_act<<<cdiv((long long)M * 1024, 256), blk>>>(H1, AC, M, 1024, 1024);
    gemm_mma<true><<<dim3(8, rt), blk, SMEM>>>(AC, W2c, b2, H2, M, 1024, 3072);
    conv_act<<<cdiv((long long)M * 1024, 256), blk>>>(H2, AC, M, 1024, 1024);
    gemm_mma<true><<<dim3(4, rt), blk, SMEM>>>(AC, W3c, b3, H3, M, 512, 3072);
    conv_act<<<cdiv((long long)M * 512, 256), blk>>>(H3, AC, M, 512, 512);
    gemm_mma<false><<<dim3(1, rt), blk, SMEM>>>(AC, W4c, b4, feat, M, 80, 1536);

    // --- GIN aggregation in 80-dim feat space: t = feat + segsum(feat[src]) ---
    k_init_t<<<cdiv(NN * 20, 256), blk>>>(feat, T, DEG, NN * 20, NN);
    k_scatter<<<cdiv((long long)EE * 20, 256), blk>>>(feat, EI, T, DEG, EE);

    // --- g = t @ Win + (1 + deg) * bin ---
    conv_act<<<cdiv((long long)M * 128, 256), blk>>>(T, AC, M, 80, 128);
    gemm_mma<false><<<dim3(4, rt), blk, SMEM>>>(AC, Winc, bin_, GG, M, 512, 384);
    k_fixup<<<cdiv((long long)NN * 128, 256), blk>>>(GG, DEG, bin_, NN);

    // --- GIN MLP ---
    conv_act<<<cdiv((long long)M * 512, 256), blk>>>(GG, AC, M, 512, 512);
    gemm_mma<true><<<dim3(4, rt), blk, SMEM>>>(AC, Wg1c, bg1, H3, M, 512, 1536);
    conv_act<<<cdiv((long long)M * 512, 256), blk>>>(H3, AC, M, 512, 512);
    gemm_mma<false><<<dim3(4, rt), blk, SMEM>>>(AC, Wg2c, bg2, GG, M, 512, 1536);

    // --- out_net ---
    conv_act<<<cdiv((long long)M * 512, 256), blk>>>(GG, AC, M, 512, 512);
    gemm_mma<false><<<dim3(1, rt), blk, SMEM>>>(AC, Woutc, bout, mask, M, 80, 1536);
}

// round 5
// speedup vs baseline: 1.8648x; 1.3815x over previous
#include <cuda_runtime.h>
#include <cuda_bf16.h>
#include <cstdint>
#include <cstddef>

#define NN 50000
#define EE 800000

// ---------------- scratch (device globals: allocation-free) ----------------
__device__ __align__(256) __nv_bfloat16 g_ac1[(size_t)NN * 3072]; // expanded ping
__device__ __align__(256) __nv_bfloat16 g_ac2[(size_t)NN * 3072]; // expanded pong
__device__ __align__(256) float g_t  [(size_t)NN * 80];           // feat + agg
__device__ __align__(256) float g_deg[NN];
__device__ __align__(256) __nv_bfloat16 g_wc[8454144];            // weight convs

// ---------------- warp-MMA helpers (baseline sm_80+ PTX only) --------------
__device__ __forceinline__ void ldsm4(uint32_t* r, uint32_t addr) {
    asm volatile("ldmatrix.sync.aligned.m8n8.x4.shared.b16 {%0,%1,%2,%3}, [%4];"
                 : "=r"(r[0]), "=r"(r[1]), "=r"(r[2]), "=r"(r[3]) : "r"(addr));
}
__device__ __forceinline__ void mma_bf16(float* c, const uint32_t* a,
                                         uint32_t b0, uint32_t b1) {
    asm volatile(
        "mma.sync.aligned.m16n8k16.row.col.f32.bf16.bf16.f32 "
        "{%0,%1,%2,%3}, {%4,%5,%6,%7}, {%8,%9}, {%0,%1,%2,%3};"
        : "+f"(c[0]), "+f"(c[1]), "+f"(c[2]), "+f"(c[3])
        : "r"(a[0]), "r"(a[1]), "r"(a[2]), "r"(a[3]), "r"(b0), "r"(b1));
}

// ---------------- bf16 tensor-core GEMM -------------------------------------
// A: [M, Kp3] bf16 row-major. Bw: [Np, Kp3] bf16 (pre-transposed, padded).
// Tile 128x128, BK=64, 3-stage cp.async pipeline, 8 warps x (64x32) warp tiles.
// SMEM rows: 64 bf16 = 128B data @ 144B pitch (9x16B, odd -> conflict-free ldsm).
// Epilogue: X3 ? write expanded [hi|lo|hi] bf16 (input of next GEMM)
//              : write fp32 (+bias, relu). DEGFIX adds deg[r]*bias[c].
template <bool RELU, bool X3, bool DEGFIX>
__global__ void __launch_bounds__(256, 2)
gemm_mma(const __nv_bfloat16* __restrict__ A, const __nv_bfloat16* __restrict__ Bw,
         const float* __restrict__ bias, float* __restrict__ Cf,
         __nv_bfloat16* __restrict__ Cx, const float* __restrict__ deg,
         int M, int Nreal, int Kp3)
{
    constexpr int STAGES = 3;
    constexpr int PITCH  = 144;           // bytes per 64-elem K row
    constexpr int TILEB  = 128 * PITCH;   // 18432
    constexpr int STAGEB = 2 * TILEB;     // 36864

    extern __shared__ char smem[];
    const uint32_t sbase = (uint32_t)__cvta_generic_to_shared(smem);

    const int tid  = threadIdx.x;
    const int lane = tid & 31;
    const int wid  = tid >> 5;
    const int wm   = wid >> 2;            // 0..1
    const int wn   = wid & 3;             // 0..3
    const int block_row = blockIdx.y * 128;
    const int block_col = blockIdx.x * 128;

    const int ld = Kp3 * 2;
    const char* Ag = (const char*)A + (size_t)block_row * ld;
    const char* Bg = (const char*)Bw + (size_t)block_col * ld;
    const int KT = Kp3 >> 6;              // chunks of 64

    // cp.async mapping: 1024 16B ops per tile, 4 per thread per tile
    const int l_row = tid >> 1;           // 0..127
    const int l_c0  = (tid & 1) * 4;      // chunk 0..3 or 4..7
    const int okA   = (block_row + l_row) < M ? 16 : 0;
    const char* ArowC = Ag + (size_t)((block_row + l_row) < M ? l_row : 0) * ld;
    const char* BrowC = Bg + (size_t)l_row * ld;

    auto load_stage = [&](int s, int kc) {
        uint32_t abuf = sbase + s * STAGEB + l_row * PITCH;
        uint32_t bbuf = abuf + TILEB;
        const char* Ak = ArowC + kc * 128;
        const char* Bk = BrowC + kc * 128;
#pragma unroll
        for (int it = 0; it < 4; it++) {
            int c = l_c0 + it;
            asm volatile("cp.async.cg.shared.global [%0], [%1], 16, %2;"
                         :: "r"(abuf + c * 16), "l"(Ak + c * 16), "r"(okA));
            asm volatile("cp.async.cg.shared.global [%0], [%1], 16;"
                         :: "r"(bbuf + c * 16), "l"(Bk + c * 16));
        }
    };

    float acc[4][4][4];
#pragma unroll
    for (int i = 0; i < 4; i++)
#pragma unroll
        for (int j = 0; j < 4; j++)
#pragma unroll
            for (int k = 0; k < 4; k++) acc[i][j][k] = 0.f;

    load_stage(0, 0);
    asm volatile("cp.async.commit_group;" ::: "memory");
    load_stage(1, 1);
    asm volatile("cp.async.commit_group;" ::: "memory");

    const uint32_t lrow = lane & 15;
    const uint32_t lhi  = (lane >> 4) << 4;
    uint32_t aoff[4], boff[2];
#pragma unroll
    for (int mt = 0; mt < 4; mt++) aoff[mt] = (wm * 64 + mt * 16 + lrow) * PITCH + lhi;
#pragma unroll
    for (int nt = 0; nt < 2; nt++) boff[nt] = (wn * 32 + nt * 16 + lrow) * PITCH + lhi;

    int slot = 0;
    for (int ks = 0; ks < KT; ks++) {
        asm volatile("cp.async.wait_group 1;" ::: "memory");
        __syncthreads();
        int kn = ks + STAGES - 1;
        int nslot = slot + 1 == STAGES ? 0 : slot + 1;
        int lslot = nslot + 1 == STAGES ? 0 : nslot + 1;
        if (kn < KT) load_stage(lslot, kn);
        asm volatile("cp.async.commit_group;" ::: "memory");

        uint32_t abuf = sbase + slot * STAGEB;
        uint32_t bbuf = abuf + TILEB;
#pragma unroll
        for (int kk = 0; kk < 4; kk++) {          // four k16 steps per chunk
            uint32_t col = kk * 32;
            uint32_t afr[4][4];
#pragma unroll
            for (int mt = 0; mt < 4; mt++)
                ldsm4(afr[mt], abuf + aoff[mt] + col);
            uint32_t bq[2][4];
#pragma unroll
            for (int nt = 0; nt < 2; nt++)
                ldsm4(bq[nt], bbuf + boff[nt] + col);
#pragma unroll
            for (int mt = 0; mt < 4; mt++)
#pragma unroll
                for (int n8 = 0; n8 < 4; n8++)
                    mma_bf16(acc[mt][n8], afr[mt],
                             bq[n8 >> 1][n8 & 1], bq[n8 >> 1][(n8 & 1) + 2]);
        }
        slot = nslot;
    }

    // epilogue
    const int g = lane >> 2, t = lane & 3;
    const size_t ldx = (size_t)3 * Nreal;
#pragma unroll
    for (int mt = 0; mt < 4; mt++) {
#pragma unroll
        for (int n8 = 0; n8 < 4; n8++) {
            int c = block_col + wn * 32 + n8 * 8 + t * 2;
            if (c >= Nreal) continue;
            float bx = __ldg(bias + c), by = __ldg(bias + c + 1);
#pragma unroll
            for (int h = 0; h < 2; h++) {
                int r = block_row + wm * 64 + mt * 16 + g + h * 8;
                if (r >= M) continue;
                float vx = acc[mt][n8][h * 2 + 0] + bx;
                float vy = acc[mt][n8][h * 2 + 1] + by;
                if (DEGFIX) {
                    float dg = __ldg(deg + r);
                    vx += dg * bx;
                    vy += dg * by;
                }
                if (RELU) { vx = fmaxf(vx, 0.f); vy = fmaxf(vy, 0.f); }
                if (X3) {
                    __nv_bfloat162 hi;
                    hi.x = __float2bfloat16(vx);
                    hi.y = __float2bfloat16(vy);
                    __nv_bfloat162 lo;
                    lo.x = __float2bfloat16(vx - __bfloat162float(hi.x));
                    lo.y = __float2bfloat16(vy - __bfloat162float(hi.y));
                    __nv_bfloat16* p = Cx + (size_t)r * ldx + c;
                    *reinterpret_cast<__nv_bfloat162*>(p) = hi;
                    *reinterpret_cast<__nv_bfloat162*>(p + Nreal) = lo;
                    *reinterpret_cast<__nv_bfloat162*>(p + 2 * Nreal) = hi;
                } else {
                    float2 v; v.x = vx; v.y = vy;
                    *reinterpret_cast<float2*>(Cf + (size_t)r * Nreal + c) = v;
                }
            }
        }
    }
}

// ---------------- fp32 -> split-bf16 [hi | lo | hi] conversion --------------
__global__ void conv_act(const float* __restrict__ in, __nv_bfloat16* __restrict__ out,
                         int M, int K, int Kp)
{
    int idx = blockIdx.x * blockDim.x + threadIdx.x;
    if (idx >= M * Kp) return;
    int r = idx / Kp;
    int k = idx - r * Kp;
    float x = (k < K) ? in[(size_t)r * K + k] : 0.f;
    __nv_bfloat16 hi = __float2bfloat16(x);
    __nv_bfloat16 lo = __float2bfloat16(x - __bfloat162float(hi));
    size_t b = (size_t)r * 3 * Kp;
    out[b + k] = hi;
    out[b + Kp + k] = lo;
    out[b + 2 * Kp + k] = hi;
}

// W[K,N] fp32 -> [Np, 3*Kp] bf16, row n = [hi | hi | lo]  (pairs with act hi|lo|hi)
__global__ void conv_wt(const float* __restrict__ W, __nv_bfloat16* __restrict__ out,
                        int K, int N, int Kp, int Np)
{
    int idx = blockIdx.x * blockDim.x + threadIdx.x;
    if (idx >= Np * Kp) return;
    int n = idx / Kp;
    int k = idx - n * Kp;
    float x = (k < K && n < N) ? W[(size_t)k * N + n] : 0.f;
    __nv_bfloat16 hi = __float2bfloat16(x);
    __nv_bfloat16 lo = __float2bfloat16(x - __bfloat162float(hi));
    size_t b = (size_t)n * 3 * Kp;
    out[b + k] = hi;
    out[b + Kp + k] = hi;
    out[b + 2 * Kp + k] = lo;
}

// ---------------- GIN aggregation on 80-dim feat ----------------------------
__global__ void k_init_t(const float* __restrict__ feat, float* __restrict__ t,
                         float* __restrict__ deg, int n4, int N)
{
    int i = blockIdx.x * blockDim.x + threadIdx.x;
    if (i < n4)
        reinterpret_cast<float4*>(t)[i] = reinterpret_cast<const float4*>(feat)[i];
    if (i < N) deg[i] = 0.f;
}

__global__ void k_scatter(const float* __restrict__ feat, const int* __restrict__ ei,
                          float* __restrict__ t, float* __restrict__ deg, int E)
{
    int i = blockIdx.x * blockDim.x + threadIdx.x;
    if (i >= E * 20) return;
    int e = i / 20;
    int c = i - e * 20;
    int s = ei[e];
    int d = ei[E + e];
    float4 v = *reinterpret_cast<const float4*>(feat + (size_t)s * 80 + c * 4);
    float* p = t + (size_t)d * 80 + c * 4;
    atomicAdd(p + 0, v.x);
    atomicAdd(p + 1, v.y);
    atomicAdd(p + 2, v.z);
    atomicAdd(p + 3, v.w);
    if (c == 0) atomicAdd(deg + d, 1.f);
}

// ---------------- launch ----------------------------------------------------
static inline unsigned cdiv(long long a, long long b) { return (unsigned)((a + b - 1) / b); }

extern "C" void kernel_launch(void* const* d_in, const int* in_sizes, int n_in,
                              void* d_out, int out_size)
{
    const float* P    = (const float*)d_in[0];
    const int*   EI   = (const int*)  d_in[1];
    const float* W1   = (const float*)d_in[2];
    const float* b1   = (const float*)d_in[3];
    const float* W2   = (const float*)d_in[4];
    const float* b2   = (const float*)d_in[5];
    const float* W3   = (const float*)d_in[6];
    const float* b3   = (const float*)d_in[7];
    const float* W4   = (const float*)d_in[8];
    const float* b4   = (const float*)d_in[9];
    const float* Win  = (const float*)d_in[10];
    const float* bin_ = (const float*)d_in[11];
    const float* Wg1  = (const float*)d_in[12];
    const float* bg1  = (const float*)d_in[13];
    const float* Wg2  = (const float*)d_in[14];
    const float* bg2  = (const float*)d_in[15];
    const float* Wout = (const float*)d_in[16];
    const float* bout = (const float*)d_in[17];

    float* out  = (float*)d_out;
    float* mask = out;
    float* feat = out + (size_t)NN * 80;

    float *T, *DEG;
    __nv_bfloat16 *AC1, *AC2, *WC;
    cudaGetSymbolAddress((void**)&T,   g_t);
    cudaGetSymbolAddress((void**)&DEG, g_deg);
    cudaGetSymbolAddress((void**)&AC1, g_ac1);
    cudaGetSymbolAddress((void**)&AC2, g_ac2);
    cudaGetSymbolAddress((void**)&WC,  g_wc);

    // weight conv buffer offsets (elements)
    __nv_bfloat16* W1c   = WC + 0;        // 1024 x 1536
    __nv_bfloat16* W2c   = WC + 1572864;  // 1024 x 3072
    __nv_bfloat16* W3c   = WC + 4718592;  // 512 x 3072
    __nv_bfloat16* W4c   = WC + 6291456;  // 128 x 1536
    __nv_bfloat16* Winc  = WC + 6488064;  // 512 x 384
    __nv_bfloat16* Wg1c  = WC + 6684672;  // 512 x 1536
    __nv_bfloat16* Wg2c  = WC + 7471104;  // 512 x 1536
    __nv_bfloat16* Woutc = WC + 8257536;  // 128 x 1536

    const int M = NN;
    const int SMEM = 3 * 2 * 128 * 144;   // 110592 B
    cudaFuncSetAttribute(gemm_mma<true,  true,  false>, cudaFuncAttributeMaxDynamicSharedMemorySize, SMEM);
    cudaFuncSetAttribute(gemm_mma<false, true,  false>, cudaFuncAttributeMaxDynamicSharedMemorySize, SMEM);
    cudaFuncSetAttribute(gemm_mma<false, true,  true >, cudaFuncAttributeMaxDynamicSharedMemorySize, SMEM);
    cudaFuncSetAttribute(gemm_mma<false, false, false>, cudaFuncAttributeMaxDynamicSharedMemorySize, SMEM);

    const dim3 blk(256);
    const unsigned rt = cdiv(M, 128);

    // --- weight conversions (tiny) ---
    conv_wt<<<cdiv(1024 * 512, 256), blk>>>(W1,   W1c,   512, 1024, 512, 1024);
    conv_wt<<<cdiv(1024 * 1024, 256), blk>>>(W2,  W2c,  1024, 1024, 1024, 1024);
    conv_wt<<<cdiv(512 * 1024, 256), blk>>>(W3,   W3c,  1024,  512, 1024,  512);
    conv_wt<<<cdiv(128 * 512, 256), blk>>>(W4,    W4c,   512,   80,  512,  128);
    conv_wt<<<cdiv(512 * 128, 256), blk>>>(Win,   Winc,   80,  512,  128,  512);
    conv_wt<<<cdiv(512 * 512, 256), blk>>>(Wg1,   Wg1c,  512,  512,  512,  512);
    conv_wt<<<cdiv(512 * 512, 256), blk>>>(Wg2,   Wg2c,  512,  512,  512,  512);
    conv_wt<<<cdiv(128 * 512, 256), blk>>>(Wout,  Woutc, 512,   80,  512,  128);

    // --- aanet_proj (expanded bf16 flows GEMM -> GEMM) ---
    conv_act<<<cdiv((long long)M * 512, 256), blk>>>(P, AC1, M, 512, 512);
    gemm_mma<true,  true,  false><<<dim3(8, rt), blk, SMEM>>>(AC1, W1c, b1, nullptr, AC2, nullptr, M, 1024, 1536);
    gemm_mma<true,  true,  false><<<dim3(8, rt), blk, SMEM>>>(AC2, W2c, b2, nullptr, AC1, nullptr, M, 1024, 3072);
    gemm_mma<true,  true,  false><<<dim3(4, rt), blk, SMEM>>>(AC1, W3c, b3, nullptr, AC2, nullptr, M, 512, 3072);
    gemm_mma<false, false, false><<<dim3(1, rt), blk, SMEM>>>(AC2, W4c, b4, feat, nullptr, nullptr, M, 80, 1536);

    // --- GIN aggregation in 80-dim feat space: t = feat + segsum(feat[src]) ---
    k_init_t<<<cdiv(NN * 20, 256), blk>>>(feat, T, DEG, NN * 20, NN);
    k_scatter<<<cdiv((long long)EE * 20, 256), blk>>>(feat, EI, T, DEG, EE);

    // --- g = t @ Win + (1 + deg) * bin  (deg fixup fused into epilogue) ---
    conv_act<<<cdiv((long long)M * 128, 256), blk>>>(T, AC1, M, 80, 128);
    gemm_mma<false, true,  true ><<<dim3(4, rt), blk, SMEM>>>(AC1, Winc, bin_, nullptr, AC2, DEG, M, 512, 384);

    // --- GIN MLP ---
    gemm_mma<true,  true,  false><<<dim3(4, rt), blk, SMEM>>>(AC2, Wg1c, bg1, nullptr, AC1, nullptr, M, 512, 1536);
    gemm_mma<false, true,  false><<<dim3(4, rt), blk, SMEM>>>(AC1, Wg2c, bg2, nullptr, AC2, nullptr, M, 512, 1536);

    // --- out_net ---
    gemm_mma<false, false, false><<<dim3(1, rt), blk, SMEM>>>(AC2, Woutc, bout, mask, nullptr, nullptr, M, 80, 1536);
}